// round 12
// baseline (speedup 1.0000x reference)
#include <cuda_runtime.h>
#include <cuda_fp16.h>
#include <cstdint>

// ---------------- static device scratch ----------------
__device__ float g_h[16*64*512];
__device__ float g_r[16*64*512];
__device__ float g_kbias[16*256*512];
__device__ __half g_kern16[201326592];     // 8192 x 24576 fp16
__device__ float g_cb[16*32*4096];
__device__ __half g_a16[8192*384];         // A' = [Ah|Al] fp16
__device__ __half g_b16[24576*384];        // B' = [Bh|Bl] fp16

__device__ __forceinline__ float lrelu(float v){ return v>=0.f ? v : 0.2f*v; }

__device__ __forceinline__ uint32_t smem_u32(const void* p){
  uint32_t a;
  asm("{ .reg .u64 t; cvta.to.shared.u64 t, %1; cvt.u32.u64 %0, t; }":"=r"(a):"l"(p));
  return a;
}
__device__ __forceinline__ void cp16(uint32_t d, const void* s){
  asm volatile("cp.async.cg.shared.global [%0], [%1], 16;"::"r"(d),"l"(s));
}
__device__ __forceinline__ void ldmx4(uint32_t* r, uint32_t a){
  asm volatile("ldmatrix.sync.aligned.m8n8.x4.shared.b16 {%0,%1,%2,%3},[%4];"
    :"=r"(r[0]),"=r"(r[1]),"=r"(r[2]),"=r"(r[3]):"r"(a));
}
__device__ __forceinline__ void mma16816(float* c, const uint32_t* a, uint32_t b0, uint32_t b1){
  asm volatile("mma.sync.aligned.m16n8k16.row.col.f32.f16.f16.f32 "
    "{%0,%1,%2,%3},{%4,%5,%6,%7},{%8,%9},{%0,%1,%2,%3};"
    :"+f"(c[0]),"+f"(c[1]),"+f"(c[2]),"+f"(c[3])
    :"r"(a[0]),"r"(a[1]),"r"(a[2]),"r"(a[3]),"r"(b0),"r"(b1));
}

// ---------------- generic small conv1d over L=512 (32-wide tiles) ----------------
template<int CI,int KS,bool RELU>
__global__ void conv1d_small(const float* __restrict__ in,const float* __restrict__ w,
    const float* __restrict__ bias,float* __restrict__ out,int Cout){
  const int PAD=(KS-1)/2, WDT=32+KS-1;
  const int l0=blockIdx.x*32, cg=blockIdx.y, b=blockIdx.z;
  __shared__ float s[CI][WDT];
  for(int idx=threadIdx.x; idx<CI*WDT; idx+=256){
    int ci=idx/WDT, p=idx-ci*WDT, l=l0+p-PAD;
    s[ci][p]=(l>=0&&l<512)?in[(b*CI+ci)*512+l]:0.f;
  }
  __syncthreads();
  const int co=cg*64+(threadIdx.x>>2), ls=(threadIdx.x&3)*8;
  float acc[8]; float bz=bias[co];
#pragma unroll
  for(int j=0;j<8;j++)acc[j]=bz;
  const float* wr=w+(size_t)co*CI*KS;
  for(int ci=0;ci<CI;ci++){
    float xv[8+KS-1];
#pragma unroll
    for(int j=0;j<8+KS-1;j++)xv[j]=s[ci][ls+j];
#pragma unroll
    for(int k=0;k<KS;k++){
      float wv=__ldg(&wr[ci*KS+k]);
#pragma unroll
      for(int j=0;j<8;j++)acc[j]=fmaf(wv,xv[j+k],acc[j]);
    }
  }
  float* orow=out+((size_t)b*Cout+co)*512+l0+ls;
#pragma unroll
  for(int j=0;j<8;j++){
    float v=acc[j];
    if(RELU)v=lrelu(v);
    orow[j]=v;
  }
}

// ---------------- all 3 residual blocks fused (halo-6 L-tiles) ----------------
__global__ void res3_fused(const float* __restrict__ in,const float* __restrict__ ws,
    const float* __restrict__ bs,float* __restrict__ out){
  const int l0=blockIdx.x*64, b=blockIdx.y, tid=threadIdx.x;
  __shared__ float xb[64][78];
  __shared__ float rb[64][78];
  for(int idx=tid; idx<64*78; idx+=256){
    int ci=idx/78, p1=idx-ci*78;
    int l=l0+p1-7;
    float v=0.f;
    if(p1>=1&&p1<=76&&l>=0&&l<512) v=in[(b*64+ci)*512+l];
    xb[ci][p1]=v; rb[ci][p1]=0.f;
  }
  __syncthreads();
  const int co=tid>>2, q=tid&3, p0=q*19;
  for(int j=0;j<3;j++){
    {
      const int st=2*j+1;
      const float* wr=ws+(size_t)(j*2)*12288+co*192;
      float bz=bs[(j*2)*64+co];
      float acc[19];
#pragma unroll
      for(int t=0;t<19;t++)acc[t]=bz;
      for(int ci=0;ci<64;ci++){
        float w0=__ldg(&wr[ci*3]),w1=__ldg(&wr[ci*3+1]),w2=__ldg(&wr[ci*3+2]);
        const float* xr=&xb[ci][p0];
#pragma unroll
        for(int t=0;t<19;t++) acc[t]+=w0*xr[t]+w1*xr[t+1]+w2*xr[t+2];
      }
#pragma unroll
      for(int t=0;t<19;t++){
        int p=p0+t, gl=l0+p-6;
        rb[co][p+1]=(p>=st&&p<=75-st&&gl>=0&&gl<512)?lrelu(acc[t]):0.f;
      }
    }
    __syncthreads();
    {
      const int st=2*j+2;
      const float* wr=ws+(size_t)(j*2+1)*12288+co*192;
      float bz=bs[(j*2+1)*64+co];
      float acc[19];
#pragma unroll
      for(int t=0;t<19;t++)acc[t]=bz;
      for(int ci=0;ci<64;ci++){
        float w0=__ldg(&wr[ci*3]),w1=__ldg(&wr[ci*3+1]),w2=__ldg(&wr[ci*3+2]);
        const float* xr=&rb[ci][p0];
#pragma unroll
        for(int t=0;t<19;t++) acc[t]+=w0*xr[t]+w1*xr[t+1]+w2*xr[t+2];
      }
      __syncthreads();
#pragma unroll
      for(int t=0;t<19;t++){
        int p=p0+t, gl=l0+p-6;
        if(p>=st&&p<=75-st&&gl>=0&&gl<512) xb[co][p+1]+=lrelu(acc[t]);
      }
    }
    __syncthreads();
  }
  for(int idx=tid; idx<64*64; idx+=256){
    int ci=idx>>6, i=idx&63;
    out[(b*64+ci)*512+l0+i]=xb[ci][i+7];
  }
}

// ---------------- combined A' + B' build (one launch) ----------------
// A' = [Ah|Al] (width 384) from im2col(g_r); B' = [Bh|Bl] (width 384) from ker_w.
__global__ void build_ab_k(const float* __restrict__ kw){
  if(blockIdx.x<6144){
    int idx=blockIdx.x*256+threadIdx.x;         // 8192*192
    int m=idx/192, kk=idx-m*192;
    int b=m>>9, l=m&511, hid=kk/3, t=kk-hid*3;
    int lp=l+t-1;
    float v=(lp>=0&&lp<512)?g_r[(b*64+hid)*512+lp]:0.f;
    __half hi=__float2half_rn(v);
    g_a16[(size_t)m*384+kk]=hi;
    g_a16[(size_t)m*384+192+kk]=__float2half_rn(v-__half2float(hi));
  }else{
    int idx=(blockIdx.x-6144)*256+threadIdx.x;  // 24576*384
    int n=idx/384, kp=idx-n*384;
    int part=(kp>=192), kk=kp-(part?192:0);
    float v=kw[(size_t)n*192+kk];
    __half hi=__float2half_rn(v);
    g_b16[idx]=part?__float2half_rn(v-__half2float(hi)):hi;
  }
}

// ---------------- mma.sync GEMM, fp16 3-pass, 512 threads, fp16 output ------------
// passes: Ah*Bh (kc 0-2), Ah*Bl (3-5), Al*Bh (6-8); kern stored as fp16.
#define ST_SZ 49152
__global__ void __launch_bounds__(512,1) gemm_mma(const float* __restrict__ kerb){
  extern __shared__ __align__(128) char smem[];
  const uint32_t sb=smem_u32(smem);
  const int tid=threadIdx.x, lane=tid&31, wid=tid>>5;
  const int wm=wid&1, wn=wid>>1;          // wn in 0..7
  const int m0=blockIdx.y*128, n0=blockIdx.x*256;
  const int acol[9]={0,64,128,0,64,128,192,256,320};
  const int bcol[9]={0,64,128,192,256,320,0,64,128};

  float acc[4][4][4];
#pragma unroll
  for(int i=0;i<4;i++)
#pragma unroll
    for(int j=0;j<4;j++)
#pragma unroll
      for(int k=0;k<4;k++)acc[i][j][k]=0.f;

  auto load_stage=[&](int kc,int st){
    uint32_t abase=sb+st*ST_SZ, bbase=abase+16384;
    const int ac=acol[kc], bc=bcol[kc];
#pragma unroll
    for(int i=0;i<2;i++){
      int q=tid+i*512, row=q>>3, c=q&7;
      cp16(abase+row*128+(((c^(row&7)))<<4),
           g_a16+(size_t)(m0+row)*384+ac+c*8);
    }
#pragma unroll
    for(int i=0;i<4;i++){
      int q=tid+i*512, row=q>>3, c=q&7;
      cp16(bbase+row*128+(((c^(row&7)))<<4),
           g_b16+(size_t)(n0+row)*384+bc+c*8);
    }
    asm volatile("cp.async.commit_group;");
  };

  load_stage(0,0);
  const int l7=lane&7;
  const int rAoff=l7+((lane>>3)&1)*8, cselA=lane>>4;
  const int rBoff=l7+((lane>>4)&1)*8, cselB=(lane>>3)&1;

  for(int kc=0;kc<9;kc++){
    if(kc<8) load_stage(kc+1,(kc+1)&1);
    if(kc<8) asm volatile("cp.async.wait_group 1;");
    else     asm volatile("cp.async.wait_group 0;");
    __syncthreads();
    uint32_t abase=sb+(kc&1)*ST_SZ, bbase=abase+16384;
#pragma unroll
    for(int ks=0;ks<4;ks++){
      const int c0=ks*2;
      uint32_t ar[4][4], br[2][4];
#pragma unroll
      for(int mi=0;mi<4;mi++){
        int row=wm*64+mi*16+rAoff;
        int cc=c0+cselA;
        ldmx4(ar[mi], abase+row*128+((cc^(row&7))<<4));
      }
#pragma unroll
      for(int np=0;np<2;np++){
        int row=wn*32+np*16+rBoff;
        int cc=c0+cselB;
        ldmx4(br[np], bbase+row*128+((cc^(row&7))<<4));
      }
#pragma unroll
      for(int mi=0;mi<4;mi++)
#pragma unroll
        for(int ni=0;ni<4;ni++)
          mma16816(acc[mi][ni], ar[mi], br[ni>>1][(ni&1)*2], br[ni>>1][(ni&1)*2+1]);
    }
    __syncthreads();
  }

  // epilogue: + ker_b, convert to fp16, streaming store
  const int g=lane>>2, t2=(lane&3)*2;
#pragma unroll
  for(int mi=0;mi<4;mi++){
    const int r0=m0+wm*64+mi*16+g;
    __half* row0=g_kern16+(size_t)r0*24576;
    __half* row1=row0+(size_t)8*24576;
#pragma unroll
    for(int ni=0;ni<4;ni++){
      int col=n0+wn*32+ni*8+t2;
      float2 bb=*(const float2*)(kerb+col);
      __half2 h0=__floats2half2_rn(acc[mi][ni][0]+bb.x, acc[mi][ni][1]+bb.y);
      __half2 h1=__floats2half2_rn(acc[mi][ni][2]+bb.x, acc[mi][ni][3]+bb.y);
      __stcs((__half2*)(row0+col),h0);
      __stcs((__half2*)(row1+col),h1);
    }
  }
}

// ---------------- convt_pre: lrelu(x) -> ConvTranspose1d(k=16, s=8, p=4) --------
__global__ void convt_pre_k(const float* __restrict__ x,const float* __restrict__ ctw,
    const float* __restrict__ ctb,float* __restrict__ xx){
  const int b=blockIdx.z, cg=blockIdx.y, t0=blockIdx.x*64, tid=threadIdx.x;
  __shared__ float swt[2048];
  __shared__ float sx[32][12];
  for(int idx=tid;idx<2048;idx+=256){
    int co_l=idx>>9, ci=(idx>>4)&31, kk=idx&15;
    swt[idx]=ctw[(ci*32+cg*4+co_l)*16+kk];
  }
  const int sbase=(t0>>3)-2;
  for(int idx=tid;idx<384;idx+=256){
    int ci=idx/12, j=idx-ci*12, sp=sbase+j;
    sx[ci][j]=(sp>=0&&sp<512)?lrelu(x[(b*32+ci)*512+sp]):0.f;
  }
  __syncthreads();
  const int co_l=tid>>6, t=t0+(tid&63), co=cg*4+co_l;
  const int k0=(8+(11-t)%8)&7;
  const int j=((t+k0-11)>>3)-sbase;
  float acc=ctb[co];
  const float* wl=&swt[co_l*512];
#pragma unroll 8
  for(int ci=0;ci<32;ci++)
    acc+=sx[ci][j]*wl[ci*16+15-k0]+sx[ci][j+1]*wl[ci*16+7-k0];
  xx[(b*32+co)*4096+t]=acc;
}

// ---------------- dilated conv block ----------------
__global__ void conv_block_k(const float* __restrict__ xx,const float* __restrict__ w,
    const float* __restrict__ bias,int dil){
  const int b=blockIdx.z, t0=blockIdx.x*128, tid=threadIdx.x;
  __shared__ float sx[32*182];
  const int W=128+2*dil;
  for(int idx=tid;idx<32*W;idx+=256){
    int ci=idx/W, p=idx-ci*W, t=t0+p-dil;
    sx[ci*182+p]=(t>=0&&t<4096)?lrelu(xx[(b*32+ci)*4096+t]):0.f;
  }
  __syncthreads();
  const int co=tid>>3, lt=(tid&7)*16;
  float acc[16]; float bz=bias[co];
#pragma unroll
  for(int j=0;j<16;j++)acc[j]=bz;
  for(int ci=0;ci<32;ci++){
    float w0=__ldg(&w[(co*32+ci)*3]);
    float w1=__ldg(&w[(co*32+ci)*3+1]);
    float w2=__ldg(&w[(co*32+ci)*3+2]);
    const float* sr=&sx[ci*182+lt];
#pragma unroll
    for(int j=0;j<16;j++)
      acc[j]+=w0*sr[j]+w1*sr[j+dil]+w2*sr[j+2*dil];
  }
  float* orow=&g_cb[(b*32+co)*4096+t0+lt];
#pragma unroll
  for(int j=0;j<16;j++)orow[j]=lrelu(acc[j]);
}

// ---------------- LVC einsum + gated residual update (fp16 kern) ----------------
__global__ void einsum_gate_k(const float* __restrict__ kbias,float* __restrict__ xx,int layer){
  const int l=blockIdx.x, b=blockIdx.y, tid=threadIdx.x;
  __shared__ __align__(16) __half sk[6144];
  __shared__ float sx[32][10];
  __shared__ float so[64][8];
  const uint4* kp=(const uint4*)(g_kern16+((size_t)(b*512+l))*24576+layer*6144);
#pragma unroll
  for(int i=0;i<3;i++) ((uint4*)sk)[tid+i*256]=__ldcs(&kp[tid+i*256]);
  for(int i=tid;i<320;i+=256){
    int ci=i/10, j=i-ci*10, t=l*8+j-1;
    sx[ci][j]=(t>=0&&t<4096)?g_cb[(b*32+ci)*4096+t]:0.f;
  }
  __syncthreads();
  const int o=tid>>2, h2=(tid&3)*2;
  float a0=0.f,a1=0.f;
#pragma unroll 4
  for(int ci=0;ci<32;ci++){
    const __half* kb=&sk[ci*192+o*3];
    float k0=__half2float(kb[0]),k1=__half2float(kb[1]),k2=__half2float(kb[2]);
    const float* xr=&sx[ci][h2];
    a0+=xr[0]*k0+xr[1]*k1+xr[2]*k2;
    a1+=xr[1]*k0+xr[2]*k1+xr[3]*k2;
  }
  const float bb=kbias[((b*4+layer)*64+o)*512+l];
  so[o][h2]=a0+bb; so[o][h2+1]=a1+bb;
  __syncthreads();
  const int co=tid>>3, h=tid&7;
  float g=1.f/(1.f+__expf(-so[co][h]));
  float th=tanhf(so[co+32][h]);
  xx[(b*32+co)*4096+l*8+h]+=g*th;
}

extern "C" void kernel_launch(void* const* d_in,const int* in_sizes,int n_in,
                              void* d_out,int out_size){
  const float* x     =(const float*)d_in[0];
  const float* c     =(const float*)d_in[1];
  const float* in_w  =(const float*)d_in[2];
  const float* in_b  =(const float*)d_in[3];
  const float* res_ws=(const float*)d_in[4];
  const float* res_bs=(const float*)d_in[5];
  const float* ker_w =(const float*)d_in[6];
  const float* ker_b =(const float*)d_in[7];
  const float* bias_w=(const float*)d_in[8];
  const float* bias_b=(const float*)d_in[9];
  const float* ct_w  =(const float*)d_in[10];
  const float* ct_b  =(const float*)d_in[11];
  const float* cb_ws =(const float*)d_in[12];
  const float* cb_bs =(const float*)d_in[13];
  float* xx=(float*)d_out;
  float *ph,*pr,*pkb;
  cudaGetSymbolAddress((void**)&ph, g_h);
  cudaGetSymbolAddress((void**)&pr, g_r);
  cudaGetSymbolAddress((void**)&pkb,g_kbias);

  cudaFuncSetAttribute(gemm_mma, cudaFuncAttributeMaxDynamicSharedMemorySize, 2*ST_SZ);

  conv1d_small<100,5,true><<<dim3(16,1,16),256>>>(c,in_w,in_b,ph,64);   // 1
  res3_fused<<<dim3(8,16),256>>>(ph,res_ws,res_bs,pr);                  // 2
  build_ab_k<<<43008,256>>>(ker_w);                                     // 3
  gemm_mma<<<dim3(96,64),512,2*ST_SZ>>>(ker_b);                         // 4 <-- profiled
  conv1d_small<64,3,false><<<dim3(16,4,16),256>>>(pr,bias_w,bias_b,pkb,256); // 5
  convt_pre_k<<<dim3(64,8,16),256>>>(x,ct_w,ct_b,xx);                   // 6
  const int dils[4]={1,3,9,27};
  for(int i=0;i<4;i++){
    conv_block_k<<<dim3(32,1,16),256>>>(xx,cb_ws+(size_t)i*3072,cb_bs+(size_t)i*32,dils[i]);
    einsum_gate_k<<<dim3(512,16),256>>>(pkb,xx,i);
  }
}

// round 14
// speedup vs baseline: 1.0888x; 1.0888x over previous
#include <cuda_runtime.h>
#include <cuda_fp16.h>
#include <cstdint>

// ---------------- static device scratch ----------------
__device__ float g_h[16*64*512];
__device__ float g_r[16*64*512];
__device__ float g_kbias[16*256*512];
__device__ float g_kern[201326592];        // 8192 x 24576 fp32
__device__ float g_cb[16*32*4096];
__device__ __half g_a16[8192*192];         // A = fp16(im2col(h))
__device__ __half g_b16[24576*384];        // B' = [Bh|Bl] fp16

__device__ __forceinline__ float lrelu(float v){ return v>=0.f ? v : 0.2f*v; }

__device__ __forceinline__ uint32_t smem_u32(const void* p){
  uint32_t a;
  asm("{ .reg .u64 t; cvta.to.shared.u64 t, %1; cvt.u32.u64 %0, t; }":"=r"(a):"l"(p));
  return a;
}
__device__ __forceinline__ void cp16(uint32_t d, const void* s){
  asm volatile("cp.async.cg.shared.global [%0], [%1], 16;"::"r"(d),"l"(s));
}
__device__ __forceinline__ void ldmx4(uint32_t* r, uint32_t a){
  asm volatile("ldmatrix.sync.aligned.m8n8.x4.shared.b16 {%0,%1,%2,%3},[%4];"
    :"=r"(r[0]),"=r"(r[1]),"=r"(r[2]),"=r"(r[3]):"r"(a));
}
__device__ __forceinline__ void mma16816(float* c, const uint32_t* a, uint32_t b0, uint32_t b1){
  asm volatile("mma.sync.aligned.m16n8k16.row.col.f32.f16.f16.f32 "
    "{%0,%1,%2,%3},{%4,%5,%6,%7},{%8,%9},{%0,%1,%2,%3};"
    :"+f"(c[0]),"+f"(c[1]),"+f"(c[2]),"+f"(c[3])
    :"r"(a[0]),"r"(a[1]),"r"(a[2]),"r"(a[3]),"r"(b0),"r"(b1));
}

// ---------------- generic small conv1d over L=512 (32-wide tiles) ----------------
template<int CI,int KS,bool RELU>
__global__ void conv1d_small(const float* __restrict__ in,const float* __restrict__ w,
    const float* __restrict__ bias,float* __restrict__ out,int Cout){
  const int PAD=(KS-1)/2, WDT=32+KS-1;
  const int l0=blockIdx.x*32, cg=blockIdx.y, b=blockIdx.z;
  __shared__ float s[CI][WDT];
  for(int idx=threadIdx.x; idx<CI*WDT; idx+=256){
    int ci=idx/WDT, p=idx-ci*WDT, l=l0+p-PAD;
    s[ci][p]=(l>=0&&l<512)?in[(b*CI+ci)*512+l]:0.f;
  }
  __syncthreads();
  const int co=cg*64+(threadIdx.x>>2), ls=(threadIdx.x&3)*8;
  float acc[8]; float bz=bias[co];
#pragma unroll
  for(int j=0;j<8;j++)acc[j]=bz;
  const float* wr=w+(size_t)co*CI*KS;
  for(int ci=0;ci<CI;ci++){
    float xv[8+KS-1];
#pragma unroll
    for(int j=0;j<8+KS-1;j++)xv[j]=s[ci][ls+j];
#pragma unroll
    for(int k=0;k<KS;k++){
      float wv=__ldg(&wr[ci*KS+k]);
#pragma unroll
      for(int j=0;j<8;j++)acc[j]=fmaf(wv,xv[j+k],acc[j]);
    }
  }
  float* orow=out+((size_t)b*Cout+co)*512+l0+ls;
#pragma unroll
  for(int j=0;j<8;j++){
    float v=acc[j];
    if(RELU)v=lrelu(v);
    orow[j]=v;
  }
}

// ---------------- all 3 residual blocks fused (halo-6 L-tiles) ----------------
__global__ void res3_fused(const float* __restrict__ in,const float* __restrict__ ws,
    const float* __restrict__ bs,float* __restrict__ out){
  const int l0=blockIdx.x*64, b=blockIdx.y, tid=threadIdx.x;
  __shared__ float xb[64][78];
  __shared__ float rb[64][78];
  for(int idx=tid; idx<64*78; idx+=256){
    int ci=idx/78, p1=idx-ci*78;
    int l=l0+p1-7;
    float v=0.f;
    if(p1>=1&&p1<=76&&l>=0&&l<512) v=in[(b*64+ci)*512+l];
    xb[ci][p1]=v; rb[ci][p1]=0.f;
  }
  __syncthreads();
  const int co=tid>>2, q=tid&3, p0=q*19;
  for(int j=0;j<3;j++){
    {
      const int st=2*j+1;
      const float* wr=ws+(size_t)(j*2)*12288+co*192;
      float bz=bs[(j*2)*64+co];
      float acc[19];
#pragma unroll
      for(int t=0;t<19;t++)acc[t]=bz;
      for(int ci=0;ci<64;ci++){
        float w0=__ldg(&wr[ci*3]),w1=__ldg(&wr[ci*3+1]),w2=__ldg(&wr[ci*3+2]);
        const float* xr=&xb[ci][p0];
#pragma unroll
        for(int t=0;t<19;t++) acc[t]+=w0*xr[t]+w1*xr[t+1]+w2*xr[t+2];
      }
#pragma unroll
      for(int t=0;t<19;t++){
        int p=p0+t, gl=l0+p-6;
        rb[co][p+1]=(p>=st&&p<=75-st&&gl>=0&&gl<512)?lrelu(acc[t]):0.f;
      }
    }
    __syncthreads();
    {
      const int st=2*j+2;
      const float* wr=ws+(size_t)(j*2+1)*12288+co*192;
      float bz=bs[(j*2+1)*64+co];
      float acc[19];
#pragma unroll
      for(int t=0;t<19;t++)acc[t]=bz;
      for(int ci=0;ci<64;ci++){
        float w0=__ldg(&wr[ci*3]),w1=__ldg(&wr[ci*3+1]),w2=__ldg(&wr[ci*3+2]);
        const float* xr=&rb[ci][p0];
#pragma unroll
        for(int t=0;t<19;t++) acc[t]+=w0*xr[t]+w1*xr[t+1]+w2*xr[t+2];
      }
      __syncthreads();
#pragma unroll
      for(int t=0;t<19;t++){
        int p=p0+t, gl=l0+p-6;
        if(p>=st&&p<=75-st&&gl>=0&&gl<512) xb[co][p+1]+=lrelu(acc[t]);
      }
    }
    __syncthreads();
  }
  for(int idx=tid; idx<64*64; idx+=256){
    int ci=idx>>6, i=idx&63;
    out[(b*64+ci)*512+l0+i]=xb[ci][i+7];
  }
}

// ---------------- combined A + B' build (one launch) ----------------
__global__ void build_ab_k(const float* __restrict__ kw){
  if(blockIdx.x<6144){
    int idx=blockIdx.x*256+threadIdx.x;         // 8192*192
    int m=idx/192, kk=idx-m*192;
    int b=m>>9, l=m&511, hid=kk/3, t=kk-hid*3;
    int lp=l+t-1;
    float v=(lp>=0&&lp<512)?g_r[(b*64+hid)*512+lp]:0.f;
    g_a16[idx]=__float2half_rn(v);
  }else{
    int idx=(blockIdx.x-6144)*256+threadIdx.x;  // 24576*384
    int n=idx/384, kp=idx-n*384;
    int part=(kp>=192), kk=kp-(part?192:0);
    float v=kw[(size_t)n*192+kk];
    __half hi=__float2half_rn(v);
    g_b16[idx]=part?__float2half_rn(v-__half2float(hi)):hi;
  }
}

// ---------------- mma.sync GEMM, fp16 2-pass, 512 threads, 3-stage pipeline -------
// per-layer launch: n0 = n_base + blockIdx.x*256 (n_base = layer*6144).
#define ST_SZ 49152
__global__ void __launch_bounds__(512,1) gemm_mma(const float* __restrict__ kerb,int n_base){
  extern __shared__ __align__(128) char smem[];
  const uint32_t sb=smem_u32(smem);
  const int tid=threadIdx.x, lane=tid&31, wid=tid>>5;
  const int wm=wid&1, wn=wid>>1;          // wn in 0..7
  const int m0=blockIdx.y*128, n0=n_base+blockIdx.x*256;

  float acc[4][4][4];
#pragma unroll
  for(int i=0;i<4;i++)
#pragma unroll
    for(int j=0;j<4;j++)
#pragma unroll
      for(int k=0;k<4;k++)acc[i][j][k]=0.f;

  auto load_stage=[&](int kc,int st){
    uint32_t abase=sb+st*ST_SZ, bbase=abase+16384;
    const int acol=(kc%3)*64;
#pragma unroll
    for(int i=0;i<2;i++){
      int q=tid+i*512, row=q>>3, c=q&7;
      cp16(abase+row*128+(((c^(row&7)))<<4),
           g_a16+(size_t)(m0+row)*192+acol+c*8);
    }
#pragma unroll
    for(int i=0;i<4;i++){
      int q=tid+i*512, row=q>>3, c=q&7;
      cp16(bbase+row*128+(((c^(row&7)))<<4),
           g_b16+(size_t)(n0+row)*384+kc*64+c*8);
    }
    asm volatile("cp.async.commit_group;");
  };

  load_stage(0,0);
  load_stage(1,1);
  const int l7=lane&7;
  const int rAoff=l7+((lane>>3)&1)*8, cselA=lane>>4;
  const int rBoff=l7+((lane>>4)&1)*8, cselB=(lane>>3)&1;

  for(int kc=0;kc<6;kc++){
    if(kc<4) asm volatile("cp.async.wait_group 1;");
    else     asm volatile("cp.async.wait_group 0;");
    __syncthreads();
    if(kc<4) load_stage(kc+2,(kc+2)%3);
    uint32_t abase=sb+(kc%3)*ST_SZ, bbase=abase+16384;
#pragma unroll
    for(int ks=0;ks<4;ks++){
      const int c0=ks*2;
      uint32_t ar[4][4], br[2][4];
#pragma unroll
      for(int mi=0;mi<4;mi++){
        int row=wm*64+mi*16+rAoff;
        int cc=c0+cselA;
        ldmx4(ar[mi], abase+row*128+((cc^(row&7))<<4));
      }
#pragma unroll
      for(int np=0;np<2;np++){
        int row=wn*32+np*16+rBoff;
        int cc=c0+cselB;
        ldmx4(br[np], bbase+row*128+((cc^(row&7))<<4));
      }
#pragma unroll
      for(int mi=0;mi<4;mi++)
#pragma unroll
        for(int ni=0;ni<4;ni++)
          mma16816(acc[mi][ni], ar[mi], br[ni>>1][(ni&1)*2], br[ni>>1][(ni&1)*2+1]);
    }
  }

  // epilogue: + ker_b -> g_kern fp32 (plain stores: keep tail in L2 for einsum)
  const int g=lane>>2, t2=(lane&3)*2;
#pragma unroll
  for(int mi=0;mi<4;mi++){
    const int r0=m0+wm*64+mi*16+g;
    float* row0=g_kern+(size_t)r0*24576;
    float* row1=row0+(size_t)8*24576;
#pragma unroll
    for(int ni=0;ni<4;ni++){
      int col=n0+wn*32+ni*8+t2;
      float2 bb=*(const float2*)(kerb+col);
      float2 v0,v1;
      v0.x=acc[mi][ni][0]+bb.x; v0.y=acc[mi][ni][1]+bb.y;
      v1.x=acc[mi][ni][2]+bb.x; v1.y=acc[mi][ni][3]+bb.y;
      *(float2*)(row0+col)=v0;
      *(float2*)(row1+col)=v1;
    }
  }
}

// ---------------- convt_pre: lrelu(x) -> ConvTranspose1d(k=16, s=8, p=4) --------
__global__ void convt_pre_k(const float* __restrict__ x,const float* __restrict__ ctw,
    const float* __restrict__ ctb,float* __restrict__ xx){
  const int b=blockIdx.z, cg=blockIdx.y, t0=blockIdx.x*64, tid=threadIdx.x;
  __shared__ float swt[2048];
  __shared__ float sx[32][12];
  for(int idx=tid;idx<2048;idx+=256){
    int co_l=idx>>9, ci=(idx>>4)&31, kk=idx&15;
    swt[idx]=ctw[(ci*32+cg*4+co_l)*16+kk];
  }
  const int sbase=(t0>>3)-2;
  for(int idx=tid;idx<384;idx+=256){
    int ci=idx/12, j=idx-ci*12, sp=sbase+j;
    sx[ci][j]=(sp>=0&&sp<512)?lrelu(x[(b*32+ci)*512+sp]):0.f;
  }
  __syncthreads();
  const int co_l=tid>>6, t=t0+(tid&63), co=cg*4+co_l;
  const int k0=(8+(11-t)%8)&7;
  const int j=((t+k0-11)>>3)-sbase;
  float acc=ctb[co];
  const float* wl=&swt[co_l*512];
#pragma unroll 8
  for(int ci=0;ci<32;ci++)
    acc+=sx[ci][j]*wl[ci*16+15-k0]+sx[ci][j+1]*wl[ci*16+7-k0];
  xx[(b*32+co)*4096+t]=acc;
}

// ---------------- dilated conv block ----------------
__global__ void conv_block_k(const float* __restrict__ xx,const float* __restrict__ w,
    const float* __restrict__ bias,int dil){
  const int b=blockIdx.z, t0=blockIdx.x*128, tid=threadIdx.x;
  __shared__ float sx[32*182];
  const int W=128+2*dil;
  for(int idx=tid;idx<32*W;idx+=256){
    int ci=idx/W, p=idx-ci*W, t=t0+p-dil;
    sx[ci*182+p]=(t>=0&&t<4096)?lrelu(xx[(b*32+ci)*4096+t]):0.f;
  }
  __syncthreads();
  const int co=tid>>3, lt=(tid&7)*16;
  float acc[16]; float bz=bias[co];
#pragma unroll
  for(int j=0;j<16;j++)acc[j]=bz;
  for(int ci=0;ci<32;ci++){
    float w0=__ldg(&w[(co*32+ci)*3]);
    float w1=__ldg(&w[(co*32+ci)*3+1]);
    float w2=__ldg(&w[(co*32+ci)*3+2]);
    const float* sr=&sx[ci*182+lt];
#pragma unroll
    for(int j=0;j<16;j++)
      acc[j]+=w0*sr[j]+w1*sr[j+dil]+w2*sr[j+2*dil];
  }
  float* orow=&g_cb[(b*32+co)*4096+t0+lt];
#pragma unroll
  for(int j=0;j<16;j++)orow[j]=lrelu(acc[j]);
}

// ---------------- LVC einsum + gated residual update (reverse order for L2 reuse) --
__global__ void einsum_gate_k(const float* __restrict__ kbias,float* __restrict__ xx,int layer){
  const int l=511-blockIdx.x, b=15-blockIdx.y, tid=threadIdx.x;
  __shared__ __align__(16) float sk[6144];
  __shared__ float sx[32][10];
  __shared__ float so[64][8];
  const float4* kp=(const float4*)(g_kern+((size_t)(b*512+l))*24576+layer*6144);
#pragma unroll
  for(int i=0;i<6;i++) ((float4*)sk)[tid+i*256]=kp[tid+i*256];
  for(int i=tid;i<320;i+=256){
    int ci=i/10, j=i-ci*10, t=l*8+j-1;
    sx[ci][j]=(t>=0&&t<4096)?g_cb[(b*32+ci)*4096+t]:0.f;
  }
  __syncthreads();
  const int o=tid>>2, h2=(tid&3)*2;
  float a0=0.f,a1=0.f;
#pragma unroll 4
  for(int ci=0;ci<32;ci++){
    const float* kb=&sk[ci*192+o*3];
    const float* xr=&sx[ci][h2];
    a0+=xr[0]*kb[0]+xr[1]*kb[1]+xr[2]*kb[2];
    a1+=xr[1]*kb[0]+xr[2]*kb[1]+xr[3]*kb[2];
  }
  const float bb=kbias[((b*4+layer)*64+o)*512+l];
  so[o][h2]=a0+bb; so[o][h2+1]=a1+bb;
  __syncthreads();
  const int co=tid>>3, h=tid&7;
  float g=1.f/(1.f+__expf(-so[co][h]));
  float th=tanhf(so[co+32][h]);
  xx[(b*32+co)*4096+l*8+h]+=g*th;
}

extern "C" void kernel_launch(void* const* d_in,const int* in_sizes,int n_in,
                              void* d_out,int out_size){
  const float* x     =(const float*)d_in[0];
  const float* c     =(const float*)d_in[1];
  const float* in_w  =(const float*)d_in[2];
  const float* in_b  =(const float*)d_in[3];
  const float* res_ws=(const float*)d_in[4];
  const float* res_bs=(const float*)d_in[5];
  const float* ker_w =(const float*)d_in[6];
  const float* ker_b =(const float*)d_in[7];
  const float* bias_w=(const float*)d_in[8];
  const float* bias_b=(const float*)d_in[9];
  const float* ct_w  =(const float*)d_in[10];
  const float* ct_b  =(const float*)d_in[11];
  const float* cb_ws =(const float*)d_in[12];
  const float* cb_bs =(const float*)d_in[13];
  float* xx=(float*)d_out;
  float *ph,*pr,*pkb;
  cudaGetSymbolAddress((void**)&ph, g_h);
  cudaGetSymbolAddress((void**)&pr, g_r);
  cudaGetSymbolAddress((void**)&pkb,g_kbias);

  cudaFuncSetAttribute(gemm_mma, cudaFuncAttributeMaxDynamicSharedMemorySize, 3*ST_SZ);

  conv1d_small<100,5,true><<<dim3(16,1,16),256>>>(c,in_w,in_b,ph,64);   // 1
  res3_fused<<<dim3(8,16),256>>>(ph,res_ws,res_bs,pr);                  // 2
  build_ab_k<<<43008,256>>>(ker_w);                                     // 3
  gemm_mma<<<dim3(24,64),512,3*ST_SZ>>>(ker_b,0);                       // 4 <-- profiled (layer 0)
  conv1d_small<64,3,false><<<dim3(16,4,16),256>>>(pr,bias_w,bias_b,pkb,256); // 5
  convt_pre_k<<<dim3(64,8,16),256>>>(x,ct_w,ct_b,xx);                   // 6
  const int dils[4]={1,3,9,27};
  for(int i=0;i<4;i++){
    if(i>0) gemm_mma<<<dim3(24,64),512,3*ST_SZ>>>(ker_b,i*6144);        // layer-i kern, hot in L2
    conv_block_k<<<dim3(32,1,16),256>>>(xx,cb_ws+(size_t)i*3072,cb_bs+(size_t)i*32,dils[i]);
    einsum_gate_k<<<dim3(512,16),256>>>(pkb,xx,i);
  }
}

// round 15
// speedup vs baseline: 1.1414x; 1.0484x over previous
#include <cuda_runtime.h>
#include <cuda_fp16.h>
#include <cstdint>

// ---------------- static device scratch ----------------
__device__ float g_h[16*64*512];
__device__ float g_r[16*64*512];
__device__ float g_kbias[16*256*512];
__device__ float g_kern[201326592];        // 8192 x 24576 fp32 (PERMUTED cols: o*96+ci*3+k)
__device__ float g_cb[16*32*4096];
__device__ float g_kbp[24576];             // permuted ker_b
__device__ __half g_a16[8192*192];         // A = fp16(im2col(h))
__device__ __half g_b16[24576*384];        // B' = [Bh|Bl] fp16, rows permuted

__device__ __forceinline__ float lrelu(float v){ return v>=0.f ? v : 0.2f*v; }

__device__ __forceinline__ uint32_t smem_u32(const void* p){
  uint32_t a;
  asm("{ .reg .u64 t; cvta.to.shared.u64 t, %1; cvt.u32.u64 %0, t; }":"=r"(a):"l"(p));
  return a;
}
__device__ __forceinline__ void cp16(uint32_t d, const void* s){
  asm volatile("cp.async.cg.shared.global [%0], [%1], 16;"::"r"(d),"l"(s));
}
__device__ __forceinline__ void ldmx4(uint32_t* r, uint32_t a){
  asm volatile("ldmatrix.sync.aligned.m8n8.x4.shared.b16 {%0,%1,%2,%3},[%4];"
    :"=r"(r[0]),"=r"(r[1]),"=r"(r[2]),"=r"(r[3]):"r"(a));
}
__device__ __forceinline__ void mma16816(float* c, const uint32_t* a, uint32_t b0, uint32_t b1){
  asm volatile("mma.sync.aligned.m16n8k16.row.col.f32.f16.f16.f32 "
    "{%0,%1,%2,%3},{%4,%5,%6,%7},{%8,%9},{%0,%1,%2,%3};"
    :"+f"(c[0]),"+f"(c[1]),"+f"(c[2]),"+f"(c[3])
    :"r"(a[0]),"r"(a[1]),"r"(a[2]),"r"(a[3]),"r"(b0),"r"(b1));
}

// ---------------- generic small conv1d over L=512 (32-wide tiles) ----------------
template<int CI,int KS,bool RELU>
__global__ void conv1d_small(const float* __restrict__ in,const float* __restrict__ w,
    const float* __restrict__ bias,float* __restrict__ out,int Cout){
  const int PAD=(KS-1)/2, WDT=32+KS-1;
  const int l0=blockIdx.x*32, cg=blockIdx.y, b=blockIdx.z;
  __shared__ float s[CI][WDT];
  for(int idx=threadIdx.x; idx<CI*WDT; idx+=256){
    int ci=idx/WDT, p=idx-ci*WDT, l=l0+p-PAD;
    s[ci][p]=(l>=0&&l<512)?in[(b*CI+ci)*512+l]:0.f;
  }
  __syncthreads();
  const int co=cg*64+(threadIdx.x>>2), ls=(threadIdx.x&3)*8;
  float acc[8]; float bz=bias[co];
#pragma unroll
  for(int j=0;j<8;j++)acc[j]=bz;
  const float* wr=w+(size_t)co*CI*KS;
  for(int ci=0;ci<CI;ci++){
    float xv[8+KS-1];
#pragma unroll
    for(int j=0;j<8+KS-1;j++)xv[j]=s[ci][ls+j];
#pragma unroll
    for(int k=0;k<KS;k++){
      float wv=__ldg(&wr[ci*KS+k]);
#pragma unroll
      for(int j=0;j<8;j++)acc[j]=fmaf(wv,xv[j+k],acc[j]);
    }
  }
  float* orow=out+((size_t)b*Cout+co)*512+l0+ls;
#pragma unroll
  for(int j=0;j<8;j++){
    float v=acc[j];
    if(RELU)v=lrelu(v);
    orow[j]=v;
  }
}

// ---------------- all 3 residual blocks fused (halo-6 L-tiles) ----------------
__global__ void res3_fused(const float* __restrict__ in,const float* __restrict__ ws,
    const float* __restrict__ bs,float* __restrict__ out){
  const int l0=blockIdx.x*64, b=blockIdx.y, tid=threadIdx.x;
  __shared__ float xb[64][78];
  __shared__ float rb[64][78];
  for(int idx=tid; idx<64*78; idx+=256){
    int ci=idx/78, p1=idx-ci*78;
    int l=l0+p1-7;
    float v=0.f;
    if(p1>=1&&p1<=76&&l>=0&&l<512) v=in[(b*64+ci)*512+l];
    xb[ci][p1]=v; rb[ci][p1]=0.f;
  }
  __syncthreads();
  const int co=tid>>2, q=tid&3, p0=q*19;
  for(int j=0;j<3;j++){
    {
      const int st=2*j+1;
      const float* wr=ws+(size_t)(j*2)*12288+co*192;
      float bz=bs[(j*2)*64+co];
      float acc[19];
#pragma unroll
      for(int t=0;t<19;t++)acc[t]=bz;
      for(int ci=0;ci<64;ci++){
        float w0=__ldg(&wr[ci*3]),w1=__ldg(&wr[ci*3+1]),w2=__ldg(&wr[ci*3+2]);
        const float* xr=&xb[ci][p0];
#pragma unroll
        for(int t=0;t<19;t++) acc[t]+=w0*xr[t]+w1*xr[t+1]+w2*xr[t+2];
      }
#pragma unroll
      for(int t=0;t<19;t++){
        int p=p0+t, gl=l0+p-6;
        rb[co][p+1]=(p>=st&&p<=75-st&&gl>=0&&gl<512)?lrelu(acc[t]):0.f;
      }
    }
    __syncthreads();
    {
      const int st=2*j+2;
      const float* wr=ws+(size_t)(j*2+1)*12288+co*192;
      float bz=bs[(j*2+1)*64+co];
      float acc[19];
#pragma unroll
      for(int t=0;t<19;t++)acc[t]=bz;
      for(int ci=0;ci<64;ci++){
        float w0=__ldg(&wr[ci*3]),w1=__ldg(&wr[ci*3+1]),w2=__ldg(&wr[ci*3+2]);
        const float* xr=&rb[ci][p0];
#pragma unroll
        for(int t=0;t<19;t++) acc[t]+=w0*xr[t]+w1*xr[t+1]+w2*xr[t+2];
      }
      __syncthreads();
#pragma unroll
      for(int t=0;t<19;t++){
        int p=p0+t, gl=l0+p-6;
        if(p>=st&&p<=75-st&&gl>=0&&gl<512) xb[co][p+1]+=lrelu(acc[t]);
      }
    }
    __syncthreads();
  }
  for(int idx=tid; idx<64*64; idx+=256){
    int ci=idx>>6, i=idx&63;
    out[(b*64+ci)*512+l0+i]=xb[ci][i+7];
  }
}

// ---------------- combined A + permuted B' + permuted bias build --------------------
// B' row n' = layer*6144 + o*96 + ci*3 + k  <- original n = layer*6144 + ci*192 + o*3 + k
__device__ __forceinline__ int perm_src(int np){
  int lay=np/6144, r=np-lay*6144;
  int o=r/96, r2=r-o*96;
  int ci=r2/3, k=r2-ci*3;
  return lay*6144+ci*192+o*3+k;
}
__global__ void build_ab_k(const float* __restrict__ kw,const float* __restrict__ kerb){
  if(blockIdx.x<6144){
    int idx=blockIdx.x*256+threadIdx.x;         // 8192*192
    int m=idx/192, kk=idx-m*192;
    int b=m>>9, l=m&511, hid=kk/3, t=kk-hid*3;
    int lp=l+t-1;
    float v=(lp>=0&&lp<512)?g_r[(b*64+hid)*512+lp]:0.f;
    g_a16[idx]=__float2half_rn(v);
  }else if(blockIdx.x<43008){
    int idx=(blockIdx.x-6144)*256+threadIdx.x;  // 24576*384
    int np=idx/384, kp=idx-np*384;
    int part=(kp>=192), kk=kp-(part?192:0);
    float v=kw[(size_t)perm_src(np)*192+kk];
    __half hi=__float2half_rn(v);
    g_b16[idx]=part?__float2half_rn(v-__half2float(hi)):hi;
  }else{
    int np=(blockIdx.x-43008)*256+threadIdx.x;  // 24576
    g_kbp[np]=kerb[perm_src(np)];
  }
}

// ---------------- mma.sync GEMM, fp16 2-pass, 512 threads (R11-proven) -------------
#define ST_SZ 49152
__global__ void __launch_bounds__(512,1) gemm_mma(){
  extern __shared__ __align__(128) char smem[];
  const uint32_t sb=smem_u32(smem);
  const int tid=threadIdx.x, lane=tid&31, wid=tid>>5;
  const int wm=wid&1, wn=wid>>1;          // wn in 0..7
  const int m0=blockIdx.y*128, n0=blockIdx.x*256;

  float acc[4][4][4];
#pragma unroll
  for(int i=0;i<4;i++)
#pragma unroll
    for(int j=0;j<4;j++)
#pragma unroll
      for(int k=0;k<4;k++)acc[i][j][k]=0.f;

  auto load_stage=[&](int kc,int st){
    uint32_t abase=sb+st*ST_SZ, bbase=abase+16384;
    const int acol=(kc%3)*64;
#pragma unroll
    for(int i=0;i<2;i++){
      int q=tid+i*512, row=q>>3, c=q&7;
      cp16(abase+row*128+(((c^(row&7)))<<4),
           g_a16+(size_t)(m0+row)*192+acol+c*8);
    }
#pragma unroll
    for(int i=0;i<4;i++){
      int q=tid+i*512, row=q>>3, c=q&7;
      cp16(bbase+row*128+(((c^(row&7)))<<4),
           g_b16+(size_t)(n0+row)*384+kc*64+c*8);
    }
    asm volatile("cp.async.commit_group;");
  };

  load_stage(0,0);
  const int l7=lane&7;
  const int rAoff=l7+((lane>>3)&1)*8, cselA=lane>>4;
  const int rBoff=l7+((lane>>4)&1)*8, cselB=(lane>>3)&1;

  for(int kc=0;kc<6;kc++){
    if(kc<5) load_stage(kc+1,(kc+1)&1);
    if(kc<5) asm volatile("cp.async.wait_group 1;");
    else     asm volatile("cp.async.wait_group 0;");
    __syncthreads();
    uint32_t abase=sb+(kc&1)*ST_SZ, bbase=abase+16384;
#pragma unroll
    for(int ks=0;ks<4;ks++){
      const int c0=ks*2;
      uint32_t ar[4][4], br[2][4];
#pragma unroll
      for(int mi=0;mi<4;mi++){
        int row=wm*64+mi*16+rAoff;
        int cc=c0+cselA;
        ldmx4(ar[mi], abase+row*128+((cc^(row&7))<<4));
      }
#pragma unroll
      for(int np=0;np<2;np++){
        int row=wn*32+np*16+rBoff;
        int cc=c0+cselB;
        ldmx4(br[np], bbase+row*128+((cc^(row&7))<<4));
      }
#pragma unroll
      for(int mi=0;mi<4;mi++)
#pragma unroll
        for(int ni=0;ni<4;ni++)
          mma16816(acc[mi][ni], ar[mi], br[ni>>1][(ni&1)*2], br[ni>>1][(ni&1)*2+1]);
    }
    __syncthreads();
  }

  // epilogue: + permuted ker_b -> g_kern (permuted layout)
  const int g=lane>>2, t2=(lane&3)*2;
#pragma unroll
  for(int mi=0;mi<4;mi++){
    const int r0=m0+wm*64+mi*16+g;
    float* row0=g_kern+(size_t)r0*24576;
    float* row1=row0+(size_t)8*24576;
#pragma unroll
    for(int ni=0;ni<4;ni++){
      int col=n0+wn*32+ni*8+t2;
      float2 bb=*(const float2*)(g_kbp+col);
      float2 v0,v1;
      v0.x=acc[mi][ni][0]+bb.x; v0.y=acc[mi][ni][1]+bb.y;
      v1.x=acc[mi][ni][2]+bb.x; v1.y=acc[mi][ni][3]+bb.y;
      *(float2*)(row0+col)=v0;
      *(float2*)(row1+col)=v1;
    }
  }
}

// ---------------- convt_pre: lrelu(x) -> ConvTranspose1d(k=16, s=8, p=4) --------
__global__ void convt_pre_k(const float* __restrict__ x,const float* __restrict__ ctw,
    const float* __restrict__ ctb,float* __restrict__ xx){
  const int b=blockIdx.z, cg=blockIdx.y, t0=blockIdx.x*64, tid=threadIdx.x;
  __shared__ float swt[2048];
  __shared__ float sx[32][12];
  for(int idx=tid;idx<2048;idx+=256){
    int co_l=idx>>9, ci=(idx>>4)&31, kk=idx&15;
    swt[idx]=ctw[(ci*32+cg*4+co_l)*16+kk];
  }
  const int sbase=(t0>>3)-2;
  for(int idx=tid;idx<384;idx+=256){
    int ci=idx/12, j=idx-ci*12, sp=sbase+j;
    sx[ci][j]=(sp>=0&&sp<512)?lrelu(x[(b*32+ci)*512+sp]):0.f;
  }
  __syncthreads();
  const int co_l=tid>>6, t=t0+(tid&63), co=cg*4+co_l;
  const int k0=(8+(11-t)%8)&7;
  const int j=((t+k0-11)>>3)-sbase;
  float acc=ctb[co];
  const float* wl=&swt[co_l*512];
#pragma unroll 8
  for(int ci=0;ci<32;ci++)
    acc+=sx[ci][j]*wl[ci*16+15-k0]+sx[ci][j+1]*wl[ci*16+7-k0];
  xx[(b*32+co)*4096+t]=acc;
}

// ---------------- dilated conv block ----------------
__global__ void conv_block_k(const float* __restrict__ xx,const float* __restrict__ w,
    const float* __restrict__ bias,int dil){
  const int b=blockIdx.z, t0=blockIdx.x*128, tid=threadIdx.x;
  __shared__ float sx[32*182];
  const int W=128+2*dil;
  for(int idx=tid;idx<32*W;idx+=256){
    int ci=idx/W, p=idx-ci*W, t=t0+p-dil;
    sx[ci*182+p]=(t>=0&&t<4096)?lrelu(xx[(b*32+ci)*4096+t]):0.f;
  }
  __syncthreads();
  const int co=tid>>3, lt=(tid&7)*16;
  float acc[16]; float bz=bias[co];
#pragma unroll
  for(int j=0;j<16;j++)acc[j]=bz;
  for(int ci=0;ci<32;ci++){
    float w0=__ldg(&w[(co*32+ci)*3]);
    float w1=__ldg(&w[(co*32+ci)*3+1]);
    float w2=__ldg(&w[(co*32+ci)*3+2]);
    const float* sr=&sx[ci*182+lt];
#pragma unroll
    for(int j=0;j<16;j++)
      acc[j]+=w0*sr[j]+w1*sr[j+dil]+w2*sr[j+2*dil];
  }
  float* orow=&g_cb[(b*32+co)*4096+t0+lt];
#pragma unroll
  for(int j=0;j<16;j++)orow[j]=lrelu(acc[j]);
}

// ---------------- LVC einsum + gate, permuted kern, reg-resident ----------------
// 256 thr = 64 o x 4 ci-quarters; kern global->reg (contiguous float4);
// cross-quarter reduce via shfl (quarters are adjacent lanes).
__global__ void einsum_gate_k(const float* __restrict__ kbias,float* __restrict__ xx,int layer){
  const int l=511-blockIdx.x, b=15-blockIdx.y, tid=threadIdx.x;
  __shared__ float sx[32][10];
  __shared__ float so[64][8];
  for(int i=tid;i<320;i+=256){
    int ci=i/10, j=i-ci*10, t=l*8+j-1;
    sx[ci][j]=(t>=0&&t<4096)?g_cb[(b*32+ci)*4096+t]:0.f;
  }
  __syncthreads();
  const int o=tid>>2, cq=tid&3;
  const float4* kp=(const float4*)(g_kern+((size_t)(b*512+l))*24576+layer*6144+o*96+cq*24);
  float kb[24];
#pragma unroll
  for(int q=0;q<6;q++){
    float4 v=kp[q];
    kb[q*4]=v.x; kb[q*4+1]=v.y; kb[q*4+2]=v.z; kb[q*4+3]=v.w;
  }
  float a[8];
#pragma unroll
  for(int h=0;h<8;h++)a[h]=0.f;
#pragma unroll
  for(int cc=0;cc<8;cc++){
    int ci=cq*8+cc;
    float k0=kb[cc*3],k1=kb[cc*3+1],k2=kb[cc*3+2];
    float xr[10];
#pragma unroll
    for(int j=0;j<10;j++)xr[j]=sx[ci][j];
#pragma unroll
    for(int h=0;h<8;h++)
      a[h]+=xr[h]*k0+xr[h+1]*k1+xr[h+2]*k2;
  }
  // reduce across cq (lanes differing in bits 0-1)
#pragma unroll
  for(int h=0;h<8;h++){
    a[h]+=__shfl_xor_sync(0xffffffff,a[h],1);
    a[h]+=__shfl_xor_sync(0xffffffff,a[h],2);
  }
  if(cq==0){
    float bb=kbias[((b*4+layer)*64+o)*512+l];
#pragma unroll
    for(int h=0;h<8;h++) so[o][h]=a[h]+bb;
  }
  __syncthreads();
  const int co=tid>>3, h=tid&7;
  float g=1.f/(1.f+__expf(-so[co][h]));
  float th=tanhf(so[co+32][h]);
  xx[(b*32+co)*4096+l*8+h]+=g*th;
}

extern "C" void kernel_launch(void* const* d_in,const int* in_sizes,int n_in,
                              void* d_out,int out_size){
  const float* x     =(const float*)d_in[0];
  const float* c     =(const float*)d_in[1];
  const float* in_w  =(const float*)d_in[2];
  const float* in_b  =(const float*)d_in[3];
  const float* res_ws=(const float*)d_in[4];
  const float* res_bs=(const float*)d_in[5];
  const float* ker_w =(const float*)d_in[6];
  const float* ker_b =(const float*)d_in[7];
  const float* bias_w=(const float*)d_in[8];
  const float* bias_b=(const float*)d_in[9];
  const float* ct_w  =(const float*)d_in[10];
  const float* ct_b  =(const float*)d_in[11];
  const float* cb_ws =(const float*)d_in[12];
  const float* cb_bs =(const float*)d_in[13];
  float* xx=(float*)d_out;
  float *ph,*pr,*pkb;
  cudaGetSymbolAddress((void**)&ph, g_h);
  cudaGetSymbolAddress((void**)&pr, g_r);
  cudaGetSymbolAddress((void**)&pkb,g_kbias);

  cudaFuncSetAttribute(gemm_mma, cudaFuncAttributeMaxDynamicSharedMemorySize, 2*ST_SZ);

  conv1d_small<100,5,true><<<dim3(16,1,16),256>>>(c,in_w,in_b,ph,64);   // 1
  res3_fused<<<dim3(8,16),256>>>(ph,res_ws,res_bs,pr);                  // 2
  build_ab_k<<<43104,256>>>(ker_w,ker_b);                               // 3
  gemm_mma<<<dim3(96,64),512,2*ST_SZ>>>();                              // 4 <-- profiled
  conv1d_small<64,3,false><<<dim3(16,4,16),256>>>(pr,bias_w,bias_b,pkb,256); // 5
  convt_pre_k<<<dim3(64,8,16),256>>>(x,ct_w,ct_b,xx);                   // 6
  const int dils[4]={1,3,9,27};
  for(int i=0;i<4;i++){
    conv_block_k<<<dim3(32,1,16),256>>>(xx,cb_ws+(size_t)i*3072,cb_bs+(size_t)i*32,dils[i]);
    einsum_gate_k<<<dim3(512,16),256>>>(pkb,xx,i);
  }
}

// round 16
// speedup vs baseline: 1.1452x; 1.0033x over previous
#include <cuda_runtime.h>
#include <cuda_fp16.h>
#include <cstdint>

// ---------------- static device scratch ----------------
__device__ float g_h[16*64*512];
__device__ float g_r[16*64*512];
__device__ float g_kbias[16*256*512];
__device__ float g_kern[201326592];        // 8192 x 24576 fp32 (PERMUTED cols: o*96+ci*3+k)
__device__ float g_cb[16*32*4096];
__device__ float g_kbp[24576];             // permuted ker_b
__device__ __half g_a16[8192*192];         // A = fp16(im2col(h))
__device__ __half g_b16[24576*384];        // B' = [Bh|Bl] fp16, rows permuted

__device__ __forceinline__ float lrelu(float v){ return v>=0.f ? v : 0.2f*v; }

__device__ __forceinline__ uint32_t smem_u32(const void* p){
  uint32_t a;
  asm("{ .reg .u64 t; cvta.to.shared.u64 t, %1; cvt.u32.u64 %0, t; }":"=r"(a):"l"(p));
  return a;
}
__device__ __forceinline__ void cp16(uint32_t d, const void* s){
  asm volatile("cp.async.cg.shared.global [%0], [%1], 16;"::"r"(d),"l"(s));
}
__device__ __forceinline__ void ldmx4(uint32_t* r, uint32_t a){
  asm volatile("ldmatrix.sync.aligned.m8n8.x4.shared.b16 {%0,%1,%2,%3},[%4];"
    :"=r"(r[0]),"=r"(r[1]),"=r"(r[2]),"=r"(r[3]):"r"(a));
}
__device__ __forceinline__ void mma16816(float* c, const uint32_t* a, uint32_t b0, uint32_t b1){
  asm volatile("mma.sync.aligned.m16n8k16.row.col.f32.f16.f16.f32 "
    "{%0,%1,%2,%3},{%4,%5,%6,%7},{%8,%9},{%0,%1,%2,%3};"
    :"+f"(c[0]),"+f"(c[1]),"+f"(c[2]),"+f"(c[3])
    :"r"(a[0]),"r"(a[1]),"r"(a[2]),"r"(a[3]),"r"(b0),"r"(b1));
}

// ---------------- generic small conv1d over L=512 (32-wide tiles) ----------------
template<int CI,int KS,bool RELU>
__global__ void conv1d_small(const float* __restrict__ in,const float* __restrict__ w,
    const float* __restrict__ bias,float* __restrict__ out,int Cout){
  const int PAD=(KS-1)/2, WDT=32+KS-1;
  const int l0=blockIdx.x*32, cg=blockIdx.y, b=blockIdx.z;
  __shared__ float s[CI][WDT];
  for(int idx=threadIdx.x; idx<CI*WDT; idx+=256){
    int ci=idx/WDT, p=idx-ci*WDT, l=l0+p-PAD;
    s[ci][p]=(l>=0&&l<512)?in[(b*CI+ci)*512+l]:0.f;
  }
  __syncthreads();
  const int co=cg*64+(threadIdx.x>>2), ls=(threadIdx.x&3)*8;
  float acc[8]; float bz=bias[co];
#pragma unroll
  for(int j=0;j<8;j++)acc[j]=bz;
  const float* wr=w+(size_t)co*CI*KS;
  for(int ci=0;ci<CI;ci++){
    float xv[8+KS-1];
#pragma unroll
    for(int j=0;j<8+KS-1;j++)xv[j]=s[ci][ls+j];
#pragma unroll
    for(int k=0;k<KS;k++){
      float wv=__ldg(&wr[ci*KS+k]);
#pragma unroll
      for(int j=0;j<8;j++)acc[j]=fmaf(wv,xv[j+k],acc[j]);
    }
  }
  float* orow=out+((size_t)b*Cout+co)*512+l0+ls;
#pragma unroll
  for(int j=0;j<8;j++){
    float v=acc[j];
    if(RELU)v=lrelu(v);
    orow[j]=v;
  }
}

// ---------------- all 3 residual blocks fused (halo-6 L-tiles) ----------------
__global__ void res3_fused(const float* __restrict__ in,const float* __restrict__ ws,
    const float* __restrict__ bs,float* __restrict__ out){
  const int l0=blockIdx.x*64, b=blockIdx.y, tid=threadIdx.x;
  __shared__ float xb[64][78];
  __shared__ float rb[64][78];
  for(int idx=tid; idx<64*78; idx+=256){
    int ci=idx/78, p1=idx-ci*78;
    int l=l0+p1-7;
    float v=0.f;
    if(p1>=1&&p1<=76&&l>=0&&l<512) v=in[(b*64+ci)*512+l];
    xb[ci][p1]=v; rb[ci][p1]=0.f;
  }
  __syncthreads();
  const int co=tid>>2, q=tid&3, p0=q*19;
  for(int j=0;j<3;j++){
    {
      const int st=2*j+1;
      const float* wr=ws+(size_t)(j*2)*12288+co*192;
      float bz=bs[(j*2)*64+co];
      float acc[19];
#pragma unroll
      for(int t=0;t<19;t++)acc[t]=bz;
      for(int ci=0;ci<64;ci++){
        float w0=__ldg(&wr[ci*3]),w1=__ldg(&wr[ci*3+1]),w2=__ldg(&wr[ci*3+2]);
        const float* xr=&xb[ci][p0];
#pragma unroll
        for(int t=0;t<19;t++) acc[t]+=w0*xr[t]+w1*xr[t+1]+w2*xr[t+2];
      }
#pragma unroll
      for(int t=0;t<19;t++){
        int p=p0+t, gl=l0+p-6;
        rb[co][p+1]=(p>=st&&p<=75-st&&gl>=0&&gl<512)?lrelu(acc[t]):0.f;
      }
    }
    __syncthreads();
    {
      const int st=2*j+2;
      const float* wr=ws+(size_t)(j*2+1)*12288+co*192;
      float bz=bs[(j*2+1)*64+co];
      float acc[19];
#pragma unroll
      for(int t=0;t<19;t++)acc[t]=bz;
      for(int ci=0;ci<64;ci++){
        float w0=__ldg(&wr[ci*3]),w1=__ldg(&wr[ci*3+1]),w2=__ldg(&wr[ci*3+2]);
        const float* xr=&rb[ci][p0];
#pragma unroll
        for(int t=0;t<19;t++) acc[t]+=w0*xr[t]+w1*xr[t+1]+w2*xr[t+2];
      }
      __syncthreads();
#pragma unroll
      for(int t=0;t<19;t++){
        int p=p0+t, gl=l0+p-6;
        if(p>=st&&p<=75-st&&gl>=0&&gl<512) xb[co][p+1]+=lrelu(acc[t]);
      }
    }
    __syncthreads();
  }
  for(int idx=tid; idx<64*64; idx+=256){
    int ci=idx>>6, i=idx&63;
    out[(b*64+ci)*512+l0+i]=xb[ci][i+7];
  }
}

// ---------------- combined A + permuted B' + permuted bias build --------------------
__device__ __forceinline__ int perm_src(int np){
  int lay=np/6144, r=np-lay*6144;
  int o=r/96, r2=r-o*96;
  int ci=r2/3, k=r2-ci*3;
  return lay*6144+ci*192+o*3+k;
}
__global__ void build_ab_k(const float* __restrict__ kw,const float* __restrict__ kerb){
  if(blockIdx.x<6144){
    int idx=blockIdx.x*256+threadIdx.x;         // 8192*192
    int m=idx/192, kk=idx-m*192;
    int b=m>>9, l=m&511, hid=kk/3, t=kk-hid*3;
    int lp=l+t-1;
    float v=(lp>=0&&lp<512)?g_r[(b*64+hid)*512+lp]:0.f;
    g_a16[idx]=__float2half_rn(v);
  }else if(blockIdx.x<43008){
    int idx=(blockIdx.x-6144)*256+threadIdx.x;  // 24576*384
    int np=idx/384, kp=idx-np*384;
    int part=(kp>=192), kk=kp-(part?192:0);
    float v=kw[(size_t)perm_src(np)*192+kk];
    __half hi=__float2half_rn(v);
    g_b16[idx]=part?__float2half_rn(v-__half2float(hi)):hi;
  }else{
    int np=(blockIdx.x-43008)*256+threadIdx.x;  // 24576
    g_kbp[np]=kerb[perm_src(np)];
  }
}

// ---------------- mma.sync GEMM, fp16 2-pass, 512 threads, per-layer n-band --------
#define ST_SZ 49152
__global__ void __launch_bounds__(512,1) gemm_mma(int n_base){
  extern __shared__ __align__(128) char smem[];
  const uint32_t sb=smem_u32(smem);
  const int tid=threadIdx.x, lane=tid&31, wid=tid>>5;
  const int wm=wid&1, wn=wid>>1;          // wn in 0..7
  const int m0=blockIdx.y*128, n0=n_base+blockIdx.x*256;

  float acc[4][4][4];
#pragma unroll
  for(int i=0;i<4;i++)
#pragma unroll
    for(int j=0;j<4;j++)
#pragma unroll
      for(int k=0;k<4;k++)acc[i][j][k]=0.f;

  auto load_stage=[&](int kc,int st){
    uint32_t abase=sb+st*ST_SZ, bbase=abase+16384;
    const int acol=(kc%3)*64;
#pragma unroll
    for(int i=0;i<2;i++){
      int q=tid+i*512, row=q>>3, c=q&7;
      cp16(abase+row*128+(((c^(row&7)))<<4),
           g_a16+(size_t)(m0+row)*192+acol+c*8);
    }
#pragma unroll
    for(int i=0;i<4;i++){
      int q=tid+i*512, row=q>>3, c=q&7;
      cp16(bbase+row*128+(((c^(row&7)))<<4),
           g_b16+(size_t)(n0+row)*384+kc*64+c*8);
    }
    asm volatile("cp.async.commit_group;");
  };

  load_stage(0,0);
  const int l7=lane&7;
  const int rAoff=l7+((lane>>3)&1)*8, cselA=lane>>4;
  const int rBoff=l7+((lane>>4)&1)*8, cselB=(lane>>3)&1;

  for(int kc=0;kc<6;kc++){
    if(kc<5) load_stage(kc+1,(kc+1)&1);
    if(kc<5) asm volatile("cp.async.wait_group 1;");
    else     asm volatile("cp.async.wait_group 0;");
    __syncthreads();
    uint32_t abase=sb+(kc&1)*ST_SZ, bbase=abase+16384;
#pragma unroll
    for(int ks=0;ks<4;ks++){
      const int c0=ks*2;
      uint32_t ar[4][4], br[2][4];
#pragma unroll
      for(int mi=0;mi<4;mi++){
        int row=wm*64+mi*16+rAoff;
        int cc=c0+cselA;
        ldmx4(ar[mi], abase+row*128+((cc^(row&7))<<4));
      }
#pragma unroll
      for(int np=0;np<2;np++){
        int row=wn*32+np*16+rBoff;
        int cc=c0+cselB;
        ldmx4(br[np], bbase+row*128+((cc^(row&7))<<4));
      }
#pragma unroll
      for(int mi=0;mi<4;mi++)
#pragma unroll
        for(int ni=0;ni<4;ni++)
          mma16816(acc[mi][ni], ar[mi], br[ni>>1][(ni&1)*2], br[ni>>1][(ni&1)*2+1]);
    }
    __syncthreads();
  }

  const int g=lane>>2, t2=(lane&3)*2;
#pragma unroll
  for(int mi=0;mi<4;mi++){
    const int r0=m0+wm*64+mi*16+g;
    float* row0=g_kern+(size_t)r0*24576;
    float* row1=row0+(size_t)8*24576;
#pragma unroll
    for(int ni=0;ni<4;ni++){
      int col=n0+wn*32+ni*8+t2;
      float2 bb=*(const float2*)(g_kbp+col);
      float2 v0,v1;
      v0.x=acc[mi][ni][0]+bb.x; v0.y=acc[mi][ni][1]+bb.y;
      v1.x=acc[mi][ni][2]+bb.x; v1.y=acc[mi][ni][3]+bb.y;
      *(float2*)(row0+col)=v0;
      *(float2*)(row1+col)=v1;
    }
  }
}

// ---------------- convt_pre: lrelu(x) -> ConvTranspose1d(k=16, s=8, p=4) --------
__global__ void convt_pre_k(const float* __restrict__ x,const float* __restrict__ ctw,
    const float* __restrict__ ctb,float* __restrict__ xx){
  const int b=blockIdx.z, cg=blockIdx.y, t0=blockIdx.x*64, tid=threadIdx.x;
  __shared__ float swt[2048];
  __shared__ float sx[32][12];
  for(int idx=tid;idx<2048;idx+=256){
    int co_l=idx>>9, ci=(idx>>4)&31, kk=idx&15;
    swt[idx]=ctw[(ci*32+cg*4+co_l)*16+kk];
  }
  const int sbase=(t0>>3)-2;
  for(int idx=tid;idx<384;idx+=256){
    int ci=idx/12, j=idx-ci*12, sp=sbase+j;
    sx[ci][j]=(sp>=0&&sp<512)?lrelu(x[(b*32+ci)*512+sp]):0.f;
  }
  __syncthreads();
  const int co_l=tid>>6, t=t0+(tid&63), co=cg*4+co_l;
  const int k0=(8+(11-t)%8)&7;
  const int j=((t+k0-11)>>3)-sbase;
  float acc=ctb[co];
  const float* wl=&swt[co_l*512];
#pragma unroll 8
  for(int ci=0;ci<32;ci++)
    acc+=sx[ci][j]*wl[ci*16+15-k0]+sx[ci][j+1]*wl[ci*16+7-k0];
  xx[(b*32+co)*4096+t]=acc;
}

// ---------------- dilated conv block ----------------
__global__ void conv_block_k(const float* __restrict__ xx,const float* __restrict__ w,
    const float* __restrict__ bias,int dil){
  const int b=blockIdx.z, t0=blockIdx.x*128, tid=threadIdx.x;
  __shared__ float sx[32*182];
  const int W=128+2*dil;
  for(int idx=tid;idx<32*W;idx+=256){
    int ci=idx/W, p=idx-ci*W, t=t0+p-dil;
    sx[ci*182+p]=(t>=0&&t<4096)?lrelu(xx[(b*32+ci)*4096+t]):0.f;
  }
  __syncthreads();
  const int co=tid>>3, lt=(tid&7)*16;
  float acc[16]; float bz=bias[co];
#pragma unroll
  for(int j=0;j<16;j++)acc[j]=bz;
  for(int ci=0;ci<32;ci++){
    float w0=__ldg(&w[(co*32+ci)*3]);
    float w1=__ldg(&w[(co*32+ci)*3+1]);
    float w2=__ldg(&w[(co*32+ci)*3+2]);
    const float* sr=&sx[ci*182+lt];
#pragma unroll
    for(int j=0;j<16;j++)
      acc[j]+=w0*sr[j]+w1*sr[j+dil]+w2*sr[j+2*dil];
  }
  float* orow=&g_cb[(b*32+co)*4096+t0+lt];
#pragma unroll
  for(int j=0;j<16;j++)orow[j]=lrelu(acc[j]);
}

// ---------------- LVC einsum + gate, permuted kern, reg-resident ----------------
__global__ void einsum_gate_k(const float* __restrict__ kbias,float* __restrict__ xx,int layer){
  const int l=511-blockIdx.x, b=15-blockIdx.y, tid=threadIdx.x;
  __shared__ float sx[32][10];
  __shared__ float so[64][8];
  for(int i=tid;i<320;i+=256){
    int ci=i/10, j=i-ci*10, t=l*8+j-1;
    sx[ci][j]=(t>=0&&t<4096)?g_cb[(b*32+ci)*4096+t]:0.f;
  }
  __syncthreads();
  const int o=tid>>2, cq=tid&3;
  const float4* kp=(const float4*)(g_kern+((size_t)(b*512+l))*24576+layer*6144+o*96+cq*24);
  float kb[24];
#pragma unroll
  for(int q=0;q<6;q++){
    float4 v=kp[q];
    kb[q*4]=v.x; kb[q*4+1]=v.y; kb[q*4+2]=v.z; kb[q*4+3]=v.w;
  }
  float a[8];
#pragma unroll
  for(int h=0;h<8;h++)a[h]=0.f;
#pragma unroll
  for(int cc=0;cc<8;cc++){
    int ci=cq*8+cc;
    float k0=kb[cc*3],k1=kb[cc*3+1],k2=kb[cc*3+2];
    float xr[10];
#pragma unroll
    for(int j=0;j<10;j++)xr[j]=sx[ci][j];
#pragma unroll
    for(int h=0;h<8;h++)
      a[h]+=xr[h]*k0+xr[h+1]*k1+xr[h+2]*k2;
  }
#pragma unroll
  for(int h=0;h<8;h++){
    a[h]+=__shfl_xor_sync(0xffffffff,a[h],1);
    a[h]+=__shfl_xor_sync(0xffffffff,a[h],2);
  }
  if(cq==0){
    float bb=kbias[((b*4+layer)*64+o)*512+l];
#pragma unroll
    for(int h=0;h<8;h++) so[o][h]=a[h]+bb;
  }
  __syncthreads();
  const int co=tid>>3, h=tid&7;
  float g=1.f/(1.f+__expf(-so[co][h]));
  float th=tanhf(so[co+32][h]);
  xx[(b*32+co)*4096+l*8+h]+=g*th;
}

extern "C" void kernel_launch(void* const* d_in,const int* in_sizes,int n_in,
                              void* d_out,int out_size){
  const float* x     =(const float*)d_in[0];
  const float* c     =(const float*)d_in[1];
  const float* in_w  =(const float*)d_in[2];
  const float* in_b  =(const float*)d_in[3];
  const float* res_ws=(const float*)d_in[4];
  const float* res_bs=(const float*)d_in[5];
  const float* ker_w =(const float*)d_in[6];
  const float* ker_b =(const float*)d_in[7];
  const float* bias_w=(const float*)d_in[8];
  const float* bias_b=(const float*)d_in[9];
  const float* ct_w  =(const float*)d_in[10];
  const float* ct_b  =(const float*)d_in[11];
  const float* cb_ws =(const float*)d_in[12];
  const float* cb_bs =(const float*)d_in[13];
  float* xx=(float*)d_out;
  float *ph,*pr,*pkb;
  cudaGetSymbolAddress((void**)&ph, g_h);
  cudaGetSymbolAddress((void**)&pr, g_r);
  cudaGetSymbolAddress((void**)&pkb,g_kbias);

  static cudaStream_t sG=nullptr;
  static cudaEvent_t evFork=nullptr, evG[4];
  static bool init=false;
  if(!init){
    cudaFuncSetAttribute(gemm_mma, cudaFuncAttributeMaxDynamicSharedMemorySize, 2*ST_SZ);
    cudaStreamCreateWithFlags(&sG, cudaStreamNonBlocking);
    cudaEventCreateWithFlags(&evFork, cudaEventDisableTiming);
    for(int i=0;i<4;i++) cudaEventCreateWithFlags(&evG[i], cudaEventDisableTiming);
    init=true;
  }

  // serial head (main/NULL stream)
  conv1d_small<100,5,true><<<dim3(16,1,16),256>>>(c,in_w,in_b,ph,64);         // 1
  res3_fused<<<dim3(8,16),256>>>(ph,res_ws,res_bs,pr);                        // 2
  build_ab_k<<<43104,256>>>(ker_w,ker_b);                                     // 3
  // fork: per-layer GEMMs on sG
  cudaEventRecord(evFork, 0);
  cudaStreamWaitEvent(sG, evFork, 0);
  for(int i=0;i<4;i++){
    gemm_mma<<<dim3(24,64),512,2*ST_SZ,sG>>>(i*6144);                         // 4..7 on sG
    cudaEventRecord(evG[i], sG);
  }
  // main stream: heads + LVC chain, overlapping the GEMMs
  conv1d_small<64,3,false><<<dim3(16,4,16),256>>>(pr,bias_w,bias_b,pkb,256);
  convt_pre_k<<<dim3(64,8,16),256>>>(x,ct_w,ct_b,xx);
  const int dils[4]={1,3,9,27};
  for(int i=0;i<4;i++){
    conv_block_k<<<dim3(32,1,16),256>>>(xx,cb_ws+(size_t)i*3072,cb_bs+(size_t)i*32,dils[i]);
    cudaStreamWaitEvent(0, evG[i], 0);     // layer-i kern ready
    einsum_gate_k<<<dim3(512,16),256>>>(pkb,xx,i);
  }
}